// round 5
// baseline (speedup 1.0000x reference)
#include <cuda_runtime.h>
#include <cstdint>

#define T_  3
#define H_  96
#define W_  96
#define C_  128
#define CK  128
#define NHEAD 8
#define DH  16
#define HW_ (H_*W_)
#define NT  (T_*HW_)        // 27648
#define QX  4
#define KPAD 132            // fp32 row stride
#define SLICE (24*KPAD)     // floats per y-slice (3 frames x 8 kx)
#define NSLOT 6
#define YSEG 16             // y rows per block
#define XS (W_/QX)          // 24 x-strips
#define YB (H_/YSEG)        // 6 y-segments

typedef unsigned long long u64;

__device__ float g_Q[NT*CK];
__device__ float g_K[NT*CK];
__device__ float g_V[NT*CK];
__device__ float g_O[NT*CK];

// ---------------- f32x2 helpers ----------------
__device__ __forceinline__ u64 ffma2(u64 a, u64 b, u64 c) {
    u64 d; asm("fma.rn.f32x2 %0,%1,%2,%3;" : "=l"(d) : "l"(a), "l"(b), "l"(c)); return d;
}
__device__ __forceinline__ u64 fadd2(u64 a, u64 b) {
    u64 d; asm("add.rn.f32x2 %0,%1,%2;" : "=l"(d) : "l"(a), "l"(b)); return d;
}
__device__ __forceinline__ u64 fmul2(u64 a, u64 b) {
    u64 d; asm("mul.rn.f32x2 %0,%1,%2;" : "=l"(d) : "l"(a), "l"(b)); return d;
}
__device__ __forceinline__ u64 pack2(float lo, float hi) {
    u64 d; asm("mov.b64 %0,{%1,%2};" : "=l"(d) : "f"(lo), "f"(hi)); return d;
}
__device__ __forceinline__ float2 unpack2(u64 v) {
    float2 r; asm("mov.b64 {%0,%1},%2;" : "=f"(r.x), "=f"(r.y) : "l"(v)); return r;
}
__device__ __forceinline__ void cp16(uint32_t dst, const float* src) {
    asm volatile("cp.async.cg.shared.global [%0], [%1], 16;" :: "r"(dst), "l"(src));
}

__device__ __forceinline__ float fexp(float x) {
    float t = fmaxf(x * 1.4426950408889634f, -125.0f);
    float r = t + 12582912.0f;
    float f = t - (r - 12582912.0f);
    int  ri = __float_as_int(r) - 0x4B400000;
    float p =              1.5403530393e-4f;
    p = fmaf(p, f, 1.3333558146e-3f);
    p = fmaf(p, f, 9.6181291076e-3f);
    p = fmaf(p, f, 5.5504108665e-2f);
    p = fmaf(p, f, 2.4022650696e-1f);
    p = fmaf(p, f, 6.9314718056e-1f);
    p = fmaf(p, f, 1.0f);
    return p * __int_as_float((ri + 127) << 23);
}

// ---------------------------------------------------------------------------
// Kernel 1: QKV projection + embedding epilogue. f32x2 inner loop.
// ---------------------------------------------------------------------------
__global__ __launch_bounds__(256) void qkv_kernel(
    const float* __restrict__ x,
    const float* __restrict__ Wq,
    const float* __restrict__ Wk,
    const float* __restrict__ Wv,
    const float* __restrict__ temp_emb,
    const float* __restrict__ sp_emb)
{
    __shared__ float xs_t[32][68];
    __shared__ float ws[32][128];

    const int which = blockIdx.y;
    const float* Wm = (which == 0) ? Wq : (which == 1) ? Wk : Wv;
    float* dst      = (which == 0) ? g_Q : (which == 1) ? g_K : g_V;

    const int m0  = blockIdx.x * 64;
    const int tid = threadIdx.x;
    const int tx  = tid & 31;
    const int ty  = tid >> 5;

    u64 acc[4][4];
#pragma unroll
    for (int p = 0; p < 4; p++)
#pragma unroll
        for (int j = 0; j < 4; j++) acc[p][j] = 0ull;

    for (int k0 = 0; k0 < 128; k0 += 32) {
        {
            int idx = tid;
#pragma unroll
            for (int it = 0; it < 2; it++) {
                int m = idx >> 3, k4 = idx & 7;
                float4 v = *(const float4*)&x[(size_t)(m0 + m) * 128 + k0 + k4 * 4];
                xs_t[k4 * 4 + 0][m] = v.x;
                xs_t[k4 * 4 + 1][m] = v.y;
                xs_t[k4 * 4 + 2][m] = v.z;
                xs_t[k4 * 4 + 3][m] = v.w;
                idx += 256;
            }
        }
        {
            int idx = tid;
#pragma unroll
            for (int it = 0; it < 4; it++) {
                int k = idx >> 5, c4 = idx & 31;
                *(float4*)&ws[k][c4 * 4] =
                    *(const float4*)&Wm[(size_t)(k0 + k) * 128 + c4 * 4];
                idx += 256;
            }
        }
        __syncthreads();
#pragma unroll
        for (int kk = 0; kk < 32; kk++) {
            float4 bv = *(const float4*)&ws[kk][tx * 4];
            u64 b0 = pack2(bv.x, bv.x), b1 = pack2(bv.y, bv.y);
            u64 b2 = pack2(bv.z, bv.z), b3 = pack2(bv.w, bv.w);
            ulonglong2 a01 = *(const ulonglong2*)&xs_t[kk][ty * 8];
            ulonglong2 a23 = *(const ulonglong2*)&xs_t[kk][ty * 8 + 4];
            acc[0][0] = ffma2(a01.x, b0, acc[0][0]);
            acc[0][1] = ffma2(a01.x, b1, acc[0][1]);
            acc[0][2] = ffma2(a01.x, b2, acc[0][2]);
            acc[0][3] = ffma2(a01.x, b3, acc[0][3]);
            acc[1][0] = ffma2(a01.y, b0, acc[1][0]);
            acc[1][1] = ffma2(a01.y, b1, acc[1][1]);
            acc[1][2] = ffma2(a01.y, b2, acc[1][2]);
            acc[1][3] = ffma2(a01.y, b3, acc[1][3]);
            acc[2][0] = ffma2(a23.x, b0, acc[2][0]);
            acc[2][1] = ffma2(a23.x, b1, acc[2][1]);
            acc[2][2] = ffma2(a23.x, b2, acc[2][2]);
            acc[2][3] = ffma2(a23.x, b3, acc[2][3]);
            acc[3][0] = ffma2(a23.y, b0, acc[3][0]);
            acc[3][1] = ffma2(a23.y, b1, acc[3][1]);
            acc[3][2] = ffma2(a23.y, b2, acc[3][2]);
            acc[3][3] = ffma2(a23.y, b3, acc[3][3]);
        }
        __syncthreads();
    }

    const int col0 = tx * 4;
#pragma unroll
    for (int p = 0; p < 4; p++) {
        float2 c0 = unpack2(acc[p][0]);
        float2 c1 = unpack2(acc[p][1]);
        float2 c2 = unpack2(acc[p][2]);
        float2 c3 = unpack2(acc[p][3]);
        float rowv[2][4] = {{c0.x, c1.x, c2.x, c3.x}, {c0.y, c1.y, c2.y, c3.y}};
#pragma unroll
        for (int rr = 0; rr < 2; rr++) {
            const int n   = m0 + ty * 8 + 2 * p + rr;
            const int t   = n / HW_;
            const int rem = n % HW_;
            if (which <= 1) {
#pragma unroll
                for (int j = 0; j < 4; j++) rowv[rr][j] += temp_emb[t * CK + col0 + j];
            }
            if (which == 0) {
                const int yq = rem / W_;
                const int xq = rem % W_;
                const int yc = min(max(yq, 2), H_ - 3);
                const int xc = min(max(xq, 2), W_ - 3);
                const int qidx = (yq - yc + 2) * 5 + (xq - xc + 2);
#pragma unroll
                for (int j = 0; j < 4; j++) rowv[rr][j] += sp_emb[qidx * CK + col0 + j];
            }
            *(float4*)&dst[(size_t)n * CK + col0] =
                make_float4(rowv[rr][0], rowv[rr][1], rowv[rr][2], rowv[rr][3]);
        }
    }
}

// ---------------------------------------------------------------------------
// Kernel 2: attention, rolling-window persistent blocks.
// Phase 1 and phase 2 share the lane layout (lane = qx*8+rl): no weight
// shuffles. Q for the next step is prefetched under phase 2.
// ---------------------------------------------------------------------------
__global__ __launch_bounds__(768) void attn_kernel(const float* __restrict__ sp_emb)
{
    extern __shared__ float sm[];
    float* Kr  = sm;                        // NSLOT x 24 x KPAD
    float* Vr  = Kr + NSLOT * SLICE;
    float* SPs = Vr + NSLOT * SLICE;        // 25 x KPAD

    const uint32_t sbase = (uint32_t)__cvta_generic_to_shared(sm);
    const uint32_t Kb  = sbase;
    const uint32_t Vb  = sbase + NSLOT * SLICE * 4;
    const uint32_t SPb = Vb + NSLOT * SLICE * 4;

    const int x0  = blockIdx.x * QX;
    const int y0  = blockIdx.y * YSEG;
    const int tid = threadIdx.x;
    const int xbase = min(max(x0, 2), W_ - 3) - 2;

    const int srow = tid >> 5;              // 0..23  = t*8 + kx
    const int sc4  = (tid & 31) * 4;
    const int st   = srow >> 3;
    const int scol = min(xbase + (srow & 7), W_ - 1);
    const size_t sgbase = (size_t)(st * HW_ + scol) * CK + sc4;
    const uint32_t ssoff = (srow * KPAD + sc4) * 4;

    for (int i = tid; i < 25 * 32; i += 768) {
        int p = i >> 5, c4 = (i & 31) * 4;
        cp16(SPb + (uint32_t)(p * KPAD + c4) * 4, &sp_emb[p * 128 + c4]);
    }
    const int yc0 = min(max(y0, 2), H_ - 3);
#pragma unroll
    for (int r = 0; r < 5; r++) {
        const int yr = yc0 - 2 + r;
        const uint32_t so = (uint32_t)((yr % NSLOT) * SLICE * 4) + ssoff;
        const size_t g = sgbase + (size_t)yr * W_ * CK;
        cp16(Kb + so, &g_K[g]);
        cp16(Vb + so, &g_V[g]);
    }
    asm volatile("cp.async.commit_group;");

    const int lane = tid & 31;
    const int w    = tid >> 5;
    const int tq   = w / NHEAD;
    const int h    = w % NHEAD;
    const int hoff = h * DH;

    const int qx  = lane >> 3;
    const int rl  = lane & 7;
    const int xoffq = min(max(x0 + qx, 2), W_ - 3) - 2 - xbase;   // 0..3
    const int kxr   = rl - xoffq;
    const bool valid = (kxr >= 0) && (kxr <= 4);
    const int kxrc  = min(max(kxr, 0), 4);

    const u64 QS = pack2(0.25f, 0.25f);

    // initial Q (pre-scaled by 0.25)
    const float* qp0 = &g_Q[(size_t)(tq * HW_ + y0 * W_ + x0 + qx) * CK + hoff];
    ulonglong2 qA = *(const ulonglong2*)&qp0[0];
    ulonglong2 qB = *(const ulonglong2*)&qp0[4];
    ulonglong2 qC = *(const ulonglong2*)&qp0[8];
    ulonglong2 qD = *(const ulonglong2*)&qp0[12];
    qA.x = fmul2(qA.x, QS); qA.y = fmul2(qA.y, QS);
    qB.x = fmul2(qB.x, QS); qB.y = fmul2(qB.y, QS);
    qC.x = fmul2(qC.x, QS); qC.y = fmul2(qC.y, QS);
    qD.x = fmul2(qD.x, QS); qD.y = fmul2(qD.y, QS);

    asm volatile("cp.async.wait_group 0;");
    __syncthreads();
    int loaded_max = yc0 + 2;

    for (int yq = y0; yq < y0 + YSEG; yq++) {
        const int yc = min(max(yq, 2), H_ - 3);

        // prefetch next K/V slice
        const int need_next = min(max(yq + 1, 2), H_ - 3) + 2;
        const bool pf = (yq + 1 < y0 + YSEG) && (need_next > loaded_max);
        if (pf) {
            const uint32_t so = (uint32_t)((need_next % NSLOT) * SLICE * 4) + ssoff;
            const size_t g = sgbase + (size_t)need_next * W_ * CK;
            cp16(Kb + so, &g_K[g]);
            cp16(Vb + so, &g_V[g]);
            asm volatile("cp.async.commit_group;");
            loaded_max = need_next;
        }

        int slot[5];
        {
            int s0 = (yc - 2) % NSLOT;
#pragma unroll
            for (int i5 = 0; i5 < 5; i5++) {
                slot[i5] = s0;
                s0 = (s0 + 1 == NSLOT) ? 0 : s0 + 1;
            }
        }

        // phase 1: Q.K (Q pre-scaled)
        float a[15];
#pragma unroll
        for (int tk = 0; tk < 3; tk++) {
#pragma unroll
            for (int i5 = 0; i5 < 5; i5++) {
                const float* kr = &Kr[slot[i5] * SLICE + (tk * 8 + rl) * KPAD + hoff];
                ulonglong2 k0 = *(const ulonglong2*)&kr[0];
                ulonglong2 k1 = *(const ulonglong2*)&kr[4];
                ulonglong2 k2 = *(const ulonglong2*)&kr[8];
                ulonglong2 k3 = *(const ulonglong2*)&kr[12];
                u64 s = ffma2(qA.x, k0.x, 0ull);
                s = ffma2(qA.y, k0.y, s);
                s = ffma2(qB.x, k1.x, s);
                s = ffma2(qB.y, k1.y, s);
                s = ffma2(qC.x, k2.x, s);
                s = ffma2(qC.y, k2.y, s);
                s = ffma2(qD.x, k3.x, s);
                s = ffma2(qD.y, k3.y, s);
                float2 f = unpack2(s);
                a[tk * 5 + i5] = f.x + f.y;
            }
        }

        // Q . sp_emb for this lane's column (Q pre-scaled)
        float qsp[5];
#pragma unroll
        for (int i5 = 0; i5 < 5; i5++) {
            const float* sp = &SPs[(i5 * 5 + kxrc) * KPAD + hoff];
            ulonglong2 s0 = *(const ulonglong2*)&sp[0];
            ulonglong2 s1 = *(const ulonglong2*)&sp[4];
            ulonglong2 s2 = *(const ulonglong2*)&sp[8];
            ulonglong2 s3 = *(const ulonglong2*)&sp[12];
            u64 s = ffma2(qA.x, s0.x, 0ull);
            s = ffma2(qA.y, s0.y, s);
            s = ffma2(qB.x, s1.x, s);
            s = ffma2(qB.y, s1.y, s);
            s = ffma2(qC.x, s2.x, s);
            s = ffma2(qC.y, s2.y, s);
            s = ffma2(qD.x, s3.x, s);
            s = ffma2(qD.y, s3.y, s);
            float2 f = unpack2(s);
            qsp[i5] = f.x + f.y;
        }

        float ssum = 0.f;
#pragma unroll
        for (int tk = 0; tk < 3; tk++)
#pragma unroll
            for (int i5 = 0; i5 < 5; i5++) {
                int idx = tk * 5 + i5;
                float e = valid ? fexp(a[idx] + qsp[i5]) : 0.f;
                a[idx] = e;
                ssum += e;
            }
        ssum += __shfl_xor_sync(0xffffffffu, ssum, 1);
        ssum += __shfl_xor_sync(0xffffffffu, ssum, 2);
        ssum += __shfl_xor_sync(0xffffffffu, ssum, 4);
        float rs = __fdividef(1.f, ssum);

        // prefetch next Q (latency hidden under phase 2)
        if (yq + 1 < y0 + YSEG) {
            const float* qn = &g_Q[(size_t)(tq * HW_ + (yq + 1) * W_ + x0 + qx) * CK + hoff];
            qA = *(const ulonglong2*)&qn[0];
            qB = *(const ulonglong2*)&qn[4];
            qC = *(const ulonglong2*)&qn[8];
            qD = *(const ulonglong2*)&qn[12];
            qA.x = fmul2(qA.x, QS); qA.y = fmul2(qA.y, QS);
            qB.x = fmul2(qB.x, QS); qB.y = fmul2(qB.y, QS);
            qC.x = fmul2(qC.x, QS); qC.y = fmul2(qC.y, QS);
            qD.x = fmul2(qD.x, QS); qD.y = fmul2(qD.y, QS);
        }

        // phase 2: AV, same lane layout (no weight shuffles)
        u64 acc[8];
#pragma unroll
        for (int i = 0; i < 8; i++) acc[i] = 0ull;
#pragma unroll
        for (int tk = 0; tk < 3; tk++) {
#pragma unroll
            for (int i5 = 0; i5 < 5; i5++) {
                const int idx = tk * 5 + i5;
                const float* vrp = &Vr[slot[i5] * SLICE + (tk * 8 + rl) * KPAD + hoff];
                ulonglong2 v0 = *(const ulonglong2*)&vrp[0];
                ulonglong2 v1 = *(const ulonglong2*)&vrp[4];
                ulonglong2 v2 = *(const ulonglong2*)&vrp[8];
                ulonglong2 v3 = *(const ulonglong2*)&vrp[12];
                u64 aa = pack2(a[idx], a[idx]);
                acc[0] = ffma2(aa, v0.x, acc[0]);
                acc[1] = ffma2(aa, v0.y, acc[1]);
                acc[2] = ffma2(aa, v1.x, acc[2]);
                acc[3] = ffma2(aa, v1.y, acc[3]);
                acc[4] = ffma2(aa, v2.x, acc[4]);
                acc[5] = ffma2(aa, v2.y, acc[5]);
                acc[6] = ffma2(aa, v3.x, acc[6]);
                acc[7] = ffma2(aa, v3.y, acc[7]);
            }
        }
        // reduce over the 8 rl lanes
#pragma unroll
        for (int off = 1; off <= 4; off <<= 1)
#pragma unroll
            for (int i = 0; i < 8; i++)
                acc[i] = fadd2(acc[i], __shfl_xor_sync(0xffffffffu, acc[i], off));

        // lane rl writes d-pair rl (7-SEL mux, no dynamic indexing)
        u64 m0 = (rl & 1) ? acc[1] : acc[0];
        u64 m1 = (rl & 1) ? acc[3] : acc[2];
        u64 m2 = (rl & 1) ? acc[5] : acc[4];
        u64 m3 = (rl & 1) ? acc[7] : acc[6];
        u64 n0 = (rl & 2) ? m1 : m0;
        u64 n1 = (rl & 2) ? m3 : m2;
        u64 sv = (rl & 4) ? n1 : n0;
        float2 pv = unpack2(sv);
        *(float2*)&g_O[(size_t)(tq * HW_ + yq * W_ + x0 + qx) * CK + hoff + rl * 2] =
            make_float2(pv.x * rs, pv.y * rs);

        if (pf) asm volatile("cp.async.wait_group 0;");
        __syncthreads();
    }
}

// ---------------------------------------------------------------------------
// Kernel 3: output projection O @ Wo, transposed writeout.
// ---------------------------------------------------------------------------
__global__ __launch_bounds__(256) void outproj_kernel(
    const float* __restrict__ Wo, float* __restrict__ out)
{
    __shared__ float xs_t[32][68];
    __shared__ float ws[32][128];

    const int m0  = blockIdx.x * 64;
    const int tid = threadIdx.x;
    const int tx  = tid & 31;
    const int ty  = tid >> 5;

    u64 acc[4][4];
#pragma unroll
    for (int p = 0; p < 4; p++)
#pragma unroll
        for (int j = 0; j < 4; j++) acc[p][j] = 0ull;

    for (int k0 = 0; k0 < 128; k0 += 32) {
        {
            int idx = tid;
#pragma unroll
            for (int it = 0; it < 2; it++) {
                int m = idx >> 3, k4 = idx & 7;
                float4 v = *(const float4*)&g_O[(size_t)(m0 + m) * 128 + k0 + k4 * 4];
                xs_t[k4 * 4 + 0][m] = v.x;
                xs_t[k4 * 4 + 1][m] = v.y;
                xs_t[k4 * 4 + 2][m] = v.z;
                xs_t[k4 * 4 + 3][m] = v.w;
                idx += 256;
            }
        }
        {
            int idx = tid;
#pragma unroll
            for (int it = 0; it < 4; it++) {
                int k = idx >> 5, c4 = idx & 31;
                *(float4*)&ws[k][c4 * 4] =
                    *(const float4*)&Wo[(size_t)(k0 + k) * 128 + c4 * 4];
                idx += 256;
            }
        }
        __syncthreads();
#pragma unroll
        for (int kk = 0; kk < 32; kk++) {
            float4 bv = *(const float4*)&ws[kk][tx * 4];
            u64 b0 = pack2(bv.x, bv.x), b1 = pack2(bv.y, bv.y);
            u64 b2 = pack2(bv.z, bv.z), b3 = pack2(bv.w, bv.w);
            ulonglong2 a01 = *(const ulonglong2*)&xs_t[kk][ty * 8];
            ulonglong2 a23 = *(const ulonglong2*)&xs_t[kk][ty * 8 + 4];
            acc[0][0] = ffma2(a01.x, b0, acc[0][0]);
            acc[0][1] = ffma2(a01.x, b1, acc[0][1]);
            acc[0][2] = ffma2(a01.x, b2, acc[0][2]);
            acc[0][3] = ffma2(a01.x, b3, acc[0][3]);
            acc[1][0] = ffma2(a01.y, b0, acc[1][0]);
            acc[1][1] = ffma2(a01.y, b1, acc[1][1]);
            acc[1][2] = ffma2(a01.y, b2, acc[1][2]);
            acc[1][3] = ffma2(a01.y, b3, acc[1][3]);
            acc[2][0] = ffma2(a23.x, b0, acc[2][0]);
            acc[2][1] = ffma2(a23.x, b1, acc[2][1]);
            acc[2][2] = ffma2(a23.x, b2, acc[2][2]);
            acc[2][3] = ffma2(a23.x, b3, acc[2][3]);
            acc[3][0] = ffma2(a23.y, b0, acc[3][0]);
            acc[3][1] = ffma2(a23.y, b1, acc[3][1]);
            acc[3][2] = ffma2(a23.y, b2, acc[3][2]);
            acc[3][3] = ffma2(a23.y, b3, acc[3][3]);
        }
        __syncthreads();
    }

    const int col0 = tx * 4;
#pragma unroll
    for (int p = 0; p < 4; p++) {
        float2 c0 = unpack2(acc[p][0]);
        float2 c1 = unpack2(acc[p][1]);
        float2 c2 = unpack2(acc[p][2]);
        float2 c3 = unpack2(acc[p][3]);
        float rowv[2][4] = {{c0.x, c1.x, c2.x, c3.x}, {c0.y, c1.y, c2.y, c3.y}};
#pragma unroll
        for (int rr = 0; rr < 2; rr++) {
            const int n   = m0 + ty * 8 + 2 * p + rr;
            const int t   = n / HW_;
            const int rem = n % HW_;
            const size_t o = (size_t)rem * (T_ * C_) + t * C_ + col0;
            *(float4*)&out[o] =
                make_float4(rowv[rr][0], rowv[rr][1], rowv[rr][2], rowv[rr][3]);
        }
    }
}

// ---------------------------------------------------------------------------
extern "C" void kernel_launch(void* const* d_in, const int* in_sizes, int n_in,
                              void* d_out, int out_size)
{
    const float* x    = (const float*)d_in[0];
    const float* Wq   = (const float*)d_in[1];
    const float* Wk   = (const float*)d_in[2];
    const float* Wv   = (const float*)d_in[3];
    const float* Wo   = (const float*)d_in[4];
    const float* temp = (const float*)d_in[5];
    const float* sp   = (const float*)d_in[6];
    float* out = (float*)d_out;

    qkv_kernel<<<dim3(NT / 64, 3), 256>>>(x, Wq, Wk, Wv, temp, sp);

    const size_t smem = (size_t)(2 * NSLOT * SLICE + 25 * KPAD) * sizeof(float);
    cudaFuncSetAttribute(attn_kernel, cudaFuncAttributeMaxDynamicSharedMemorySize, (int)smem);
    attn_kernel<<<dim3(XS, YB), 768, smem>>>(sp);

    outproj_kernel<<<NT / 64, 256>>>(Wo, out);
}